// round 14
// baseline (speedup 1.0000x reference)
#include <cuda_runtime.h>
#include <cuda_bf16.h>
#include <cuda_fp16.h>
#include <cstdint>

#define B_DIM 4096
#define DIN   4096
#define DBN   32768
#define KSEL  64
#define CAND  80
#define BUF_CAP 1024
#define L2_CAP 512
#define FILTER_KEY 0xC000u   // monotonic key of +2.0 (bf16)

// ---------------- scratch (device globals: allocation-free) ----------------
__device__ __nv_bfloat16 g_xb[(size_t)B_DIM * DIN];   // 32 MB  (GEMM A, bf16)
__device__ __nv_bfloat16 g_wb[(size_t)DBN * DIN];     // 256 MB (GEMM B, bf16)
__device__ __half        g_wh[(size_t)DBN * DIN];     // 256 MB (decode weights, fp16)
__device__ __nv_bfloat16 g_a1[(size_t)B_DIM * DBN];   // 256 MB (bf16 scores)
__device__ int           g_cand[(size_t)B_DIM * CAND];

// ---------------- K0: fp32 -> bf16 (x, W) + fp16 (W) convert (EXACT R10) ----------------
__global__ void convert_kernel(const float* __restrict__ x, const float* __restrict__ w) {
    size_t nx = (size_t)B_DIM * DIN / 4;
    size_t nw = (size_t)DBN * DIN / 4;
    size_t stride = (size_t)gridDim.x * blockDim.x;
    for (size_t t = (size_t)blockIdx.x * blockDim.x + threadIdx.x; t < nx + nw; t += stride) {
        if (t < nx) {
            float4 v = ((const float4*)x)[t];
            __nv_bfloat162* o = reinterpret_cast<__nv_bfloat162*>(g_xb);
            o[2 * t]     = __floats2bfloat162_rn(v.x, v.y);
            o[2 * t + 1] = __floats2bfloat162_rn(v.z, v.w);
        } else {
            size_t u = t - nx;
            float4 v = ((const float4*)w)[u];
            __nv_bfloat162* ob = reinterpret_cast<__nv_bfloat162*>(g_wb);
            ob[2 * u]     = __floats2bfloat162_rn(v.x, v.y);
            ob[2 * u + 1] = __floats2bfloat162_rn(v.z, v.w);
            __half2* oh = reinterpret_cast<__half2*>(g_wh);
            oh[2 * u]     = __floats2half2_rn(v.x, v.y);
            oh[2 * u + 1] = __floats2half2_rn(v.z, v.w);
        }
    }
}

// ---------------- K1: bf16 encode GEMM (EXACT R10) ----------------
__device__ __forceinline__ unsigned sw_off(int row, int c) {
    return (unsigned)(row * 64 + ((c ^ ((row >> 1) & 3)) << 4));
}

__global__ void __launch_bounds__(256) encode_gemm(const float* __restrict__ b_enc) {
    const int m0 = blockIdx.x * 128;
    const int n0 = blockIdx.y * 128;

    __shared__ __align__(16) __nv_bfloat16 sA[2][128 * 32];
    __shared__ __align__(16) __nv_bfloat16 sB[2][128 * 32];

    const int tid = threadIdx.x;
    const int wid = tid >> 5, lane = tid & 31;
    const int wm = wid >> 2, wn = wid & 3;

    unsigned sA_base = (unsigned)__cvta_generic_to_shared(&sA[0][0]);
    unsigned sB_base = (unsigned)__cvta_generic_to_shared(&sB[0][0]);

    const __nv_bfloat16* gA = g_xb + (size_t)m0 * DIN;
    const __nv_bfloat16* gB = g_wb + (size_t)n0 * DIN;

    float acc[4][4][4];
#pragma unroll
    for (int i = 0; i < 4; i++)
#pragma unroll
        for (int j = 0; j < 4; j++)
#pragma unroll
            for (int r = 0; r < 4; r++) acc[i][j][r] = 0.f;

#define LOAD_TILE(buf, kt)                                                              \
    do {                                                                                \
        _Pragma("unroll")                                                               \
        for (int _i = 0; _i < 2; _i++) {                                                \
            int cid = tid + 256 * _i;                                                   \
            int row = cid >> 2, c = cid & 3;                                            \
            unsigned off = sw_off(row, c);                                              \
            const __nv_bfloat16* srcA = gA + (size_t)row * DIN + (kt) + c * 8;          \
            const __nv_bfloat16* srcB = gB + (size_t)row * DIN + (kt) + c * 8;          \
            unsigned da = sA_base + (buf) * 8192u + off;                                \
            unsigned db = sB_base + (buf) * 8192u + off;                                \
            asm volatile("cp.async.cg.shared.global [%0],[%1],16;\n" ::"r"(da), "l"(srcA)); \
            asm volatile("cp.async.cg.shared.global [%0],[%1],16;\n" ::"r"(db), "l"(srcB)); \
        }                                                                               \
        asm volatile("cp.async.commit_group;\n");                                      \
    } while (0)

    LOAD_TILE(0, 0);
    const int NT = DIN / 32;
    for (int t = 0; t < NT; t++) {
        if (t + 1 < NT) {
            LOAD_TILE((t + 1) & 1, (t + 1) * 32);
            asm volatile("cp.async.wait_group 1;\n");
        } else {
            asm volatile("cp.async.wait_group 0;\n");
        }
        __syncthreads();
        const int buf = t & 1;
#pragma unroll
        for (int ks = 0; ks < 2; ks++) {
            unsigned a[4][4];
#pragma unroll
            for (int i = 0; i < 4; i++) {
                int row = wm * 64 + i * 16 + (lane & 7) + ((lane >> 3) & 1) * 8;
                int c   = ks * 2 + (lane >> 4);
                unsigned addr = sA_base + buf * 8192u + sw_off(row, c);
                asm volatile("ldmatrix.sync.aligned.m8n8.x4.shared.b16 {%0,%1,%2,%3},[%4];\n"
                             : "=r"(a[i][0]), "=r"(a[i][1]), "=r"(a[i][2]), "=r"(a[i][3])
                             : "r"(addr));
            }
            unsigned b[4][2];
#pragma unroll
            for (int jj = 0; jj < 2; jj++) {
                int row = wn * 32 + jj * 16 + ((lane >> 4) & 1) * 8 + (lane & 7);
                int c   = ks * 2 + ((lane >> 3) & 1);
                unsigned addr = sB_base + buf * 8192u + sw_off(row, c);
                unsigned r0, r1, r2, r3;
                asm volatile("ldmatrix.sync.aligned.m8n8.x4.shared.b16 {%0,%1,%2,%3},[%4];\n"
                             : "=r"(r0), "=r"(r1), "=r"(r2), "=r"(r3)
                             : "r"(addr));
                b[2 * jj][0] = r0; b[2 * jj][1] = r1;
                b[2 * jj + 1][0] = r2; b[2 * jj + 1][1] = r3;
            }
#pragma unroll
            for (int i = 0; i < 4; i++)
#pragma unroll
                for (int j = 0; j < 4; j++) {
                    asm volatile(
                        "mma.sync.aligned.m16n8k16.row.col.f32.bf16.bf16.f32 "
                        "{%0,%1,%2,%3},{%4,%5,%6,%7},{%8,%9},{%0,%1,%2,%3};\n"
                        : "+f"(acc[i][j][0]), "+f"(acc[i][j][1]),
                          "+f"(acc[i][j][2]), "+f"(acc[i][j][3])
                        : "r"(a[i][0]), "r"(a[i][1]), "r"(a[i][2]), "r"(a[i][3]),
                          "r"(b[j][0]), "r"(b[j][1]));
                }
        }
        __syncthreads();
    }
#undef LOAD_TILE

    const int mrow = m0 + wm * 64;
    const int ncol = n0 + wn * 32;
#pragma unroll
    for (int i = 0; i < 4; i++) {
#pragma unroll
        for (int j = 0; j < 4; j++) {
            int r  = mrow + i * 16 + (lane >> 2);
            int cc = ncol + j * 8 + (lane & 3) * 2;
            float be0 = __ldg(&b_enc[cc]);
            float be1 = __ldg(&b_enc[cc + 1]);
            __nv_bfloat162 v0 = __floats2bfloat162_rn(acc[i][j][0] + be0, acc[i][j][1] + be1);
            __nv_bfloat162 v1 = __floats2bfloat162_rn(acc[i][j][2] + be0, acc[i][j][3] + be1);
            *reinterpret_cast<__nv_bfloat162*>(&g_a1[(size_t)r * DBN + cc])       = v0;
            *reinterpret_cast<__nv_bfloat162*>(&g_a1[(size_t)(r + 8) * DBN + cc]) = v1;
        }
    }
}

// ---------------- K2: filtered top-CAND, exact per-bf16-code bins (R13-validated) ----------------
__device__ __forceinline__ unsigned fkey16(unsigned u) {
    u &= 0xFFFFu;
    return (u & 0x8000u) ? ((~u) & 0xFFFFu) : (u | 0x8000u);  // order-preserving
}

__global__ void __launch_bounds__(256) topk_kernel() {
    const int row = blockIdx.x;
    const int tid = threadIdx.x;

    __shared__ unsigned buf[BUF_CAP];
    __shared__ unsigned list2[L2_CAP];
    __shared__ unsigned hist[4096];
    __shared__ int bcnt, mcnt;
    __shared__ unsigned s_tbin;

    if (tid == 0) { bcnt = 0; mcnt = 0; }
    for (int i = tid; i < 4096; i += 256) hist[i] = 0;
    __syncthreads();

    const uint4* p4 = reinterpret_cast<const uint4*>(g_a1 + (size_t)row * DBN);
#pragma unroll 4
    for (int j = 0; j < 16; j++) {
        int vi = tid + 256 * j;
        uint4 v = p4[vi];
        unsigned w[4] = {v.x, v.y, v.z, v.w};
        int base = vi * 8;
#pragma unroll
        for (int q = 0; q < 4; q++) {
            unsigned k0 = fkey16(w[q]);
            unsigned k1 = fkey16(w[q] >> 16);
            if (k0 >= FILTER_KEY) {
                int pos = atomicAdd(&bcnt, 1);
                if (pos < BUF_CAP) buf[pos] = (k0 << 16) | (unsigned)(base + 2 * q);
            }
            if (k1 >= FILTER_KEY) {
                int pos = atomicAdd(&bcnt, 1);
                if (pos < BUF_CAP) buf[pos] = (k1 << 16) | (unsigned)(base + 2 * q + 1);
            }
        }
    }
    __syncthreads();

    bool fast_ok = (bcnt >= CAND && bcnt <= BUF_CAP);
    if (fast_ok) {
        const int n = bcnt;
        for (int e = tid; e < n; e += 256) {
            unsigned bin = (buf[e] >> 16) - FILTER_KEY;
            if (bin > 4095u) bin = 4095u;
            atomicAdd(&hist[bin], 1u);
        }
        __syncthreads();
        if (tid == 0) {
            unsigned cum = 0;
            int b = 4095;
            for (; b > 0; b--) {
                unsigned c = hist[b];
                if (cum + c >= CAND) break;
                cum += c;
            }
            s_tbin = (unsigned)b;
        }
        __syncthreads();
        const unsigned tb = s_tbin;
        for (int e = tid; e < n; e += 256) {
            const unsigned pe = buf[e];
            unsigned bin = (pe >> 16) - FILTER_KEY;
            if (bin > 4095u) bin = 4095u;
            if (bin >= tb) {
                int pos = atomicAdd(&mcnt, 1);
                if (pos < L2_CAP) list2[pos] = pe;
            }
        }
        __syncthreads();
        if (mcnt <= L2_CAP) {
            const int m = mcnt;
            for (int e = tid; e < m; e += 256) {
                const unsigned pe = list2[e];
                int rank = 0;
                for (int j2 = 0; j2 < m; j2++) rank += (list2[j2] > pe);
                if (rank < CAND) g_cand[(size_t)row * CAND + rank] = (int)(pe & 0xFFFFu);
            }
            return;
        }
    }

    // -------- fallback: full 4096-bin histogram (distribution-free) --------
    __syncthreads();
    for (int i = tid; i < 4096; i += 256) hist[i] = 0;
    if (tid == 0) { bcnt = 0; }
    __syncthreads();
#pragma unroll 4
    for (int j = 0; j < 16; j++) {
        uint4 v = p4[tid + 256 * j];
        unsigned w[4] = {v.x, v.y, v.z, v.w};
#pragma unroll
        for (int q = 0; q < 4; q++) {
            atomicAdd(&hist[fkey16(w[q]) >> 4], 1u);
            atomicAdd(&hist[fkey16(w[q] >> 16) >> 4], 1u);
        }
    }
    __syncthreads();
    if (tid == 0) {
        unsigned cum = 0;
        int b = 4095;
        for (; b > 0; b--) {
            unsigned c = hist[b];
            if (cum + c >= CAND) break;
            cum += c;
        }
        s_tbin = (unsigned)b;
    }
    __syncthreads();
    const unsigned tb = s_tbin;
#pragma unroll 4
    for (int j = 0; j < 16; j++) {
        int vi = tid + 256 * j;
        uint4 v = p4[vi];
        unsigned w[4] = {v.x, v.y, v.z, v.w};
        int base = vi * 8;
#pragma unroll
        for (int q = 0; q < 4; q++) {
            unsigned k0 = fkey16(w[q]);
            unsigned k1 = fkey16(w[q] >> 16);
            if ((k0 >> 4) >= tb) {
                int pos = atomicAdd(&bcnt, 1);
                if (pos < BUF_CAP) buf[pos] = (k0 << 16) | (unsigned)(base + 2 * q);
            }
            if ((k1 >> 4) >= tb) {
                int pos = atomicAdd(&bcnt, 1);
                if (pos < BUF_CAP) buf[pos] = (k1 << 16) | (unsigned)(base + 2 * q + 1);
            }
        }
    }
    __syncthreads();
    const int n2 = bcnt < BUF_CAP ? bcnt : BUF_CAP;
    for (int e = tid; e < n2; e += 256) {
        const unsigned pe = buf[e];
        int rank = 0;
        for (int j2 = 0; j2 < n2; j2++) rank += (buf[j2] > pe);
        if (rank < CAND) g_cand[(size_t)row * CAND + rank] = (int)(pe & 0xFFFFu);
    }
}

// ---------------- K3: fused exact-rescore + top-64 + fp16-weight decode (EXACT R10) ----------------
__global__ void __launch_bounds__(256) rescore_decode_kernel(
    const float* __restrict__ x, const float* __restrict__ W,
    const float* __restrict__ b_enc, const float* __restrict__ b_dec,
    float* __restrict__ out) {
    const int row = blockIdx.x;
    const int tid = threadIdx.x;
    const int wid = tid >> 5, lane = tid & 31;

    __shared__ float  sx[DIN];
    __shared__ double sval[CAND];
    __shared__ int    scan_[CAND];
    __shared__ float  sv[KSEL];
    __shared__ int    si[KSEL];
    __shared__ int    cnt;

    const float4* xg  = reinterpret_cast<const float4*>(x + (size_t)row * DIN);
    float4*       sx4 = reinterpret_cast<float4*>(sx);
    for (int i = tid; i < DIN / 4; i += 256) sx4[i] = xg[i];
    if (tid == 0) cnt = 0;
    __syncthreads();

    for (int c = wid; c < CAND; c += 8) {
        const int idx = g_cand[(size_t)row * CAND + c];
        const float4* wv = reinterpret_cast<const float4*>(W + (size_t)idx * DIN);
        float s0 = 0.f, c0 = 0.f, s1 = 0.f, c1 = 0.f;
#define ACC(ss, cc, aa, bb)                              \
        {                                                \
            float p = (aa) * (bb);                       \
            float e = __fmaf_rn((aa), (bb), -p);         \
            float t = ss + p;                            \
            cc += (ss - t) + p;                          \
            ss = t;                                      \
            cc += e;                                     \
        }
        for (int i = lane; i < DIN / 4; i += 32) {
            float4 w = wv[i], xx = sx4[i];
            ACC(s0, c0, w.x, xx.x) ACC(s1, c1, w.y, xx.y)
            ACC(s0, c0, w.z, xx.z) ACC(s1, c1, w.w, xx.w)
        }
#undef ACC
        double d = ((double)s0 + (double)c0) + ((double)s1 + (double)c1);
#pragma unroll
        for (int o = 16; o; o >>= 1) d += __shfl_xor_sync(0xFFFFFFFFu, d, o);
        if (lane == 0) { sval[c] = d + (double)b_enc[idx]; scan_[c] = idx; }
    }
    __syncthreads();

    if (tid < CAND) {
        const double v = sval[tid];
        const int   ii = scan_[tid];
        int greater = 0;
        for (int j = 0; j < CAND; j++) {
            double u = sval[j];
            if (u > v || (u == v && scan_[j] < ii)) greater++;
        }
        if (greater < KSEL) {
            int slot = atomicAdd(&cnt, 1);
            sv[slot] = (float)v;
            si[slot] = ii;
        }
    }
    __syncthreads();

    const float4* bd = reinterpret_cast<const float4*>(b_dec);
    float4 acc[4];
#pragma unroll
    for (int s = 0; s < 4; s++) acc[s] = bd[tid + s * 256];

    for (int j = 0; j < KSEL; j++) {
        const float v = sv[j];
        const uint2* wr = reinterpret_cast<const uint2*>(g_wh + (size_t)si[j] * DIN);
#pragma unroll
        for (int s = 0; s < 4; s++) {
            uint2 hw = wr[tid + s * 256];
            float2 lo = __half22float2(*reinterpret_cast<__half2*>(&hw.x));
            float2 hi = __half22float2(*reinterpret_cast<__half2*>(&hw.y));
            acc[s].x += v * lo.x; acc[s].y += v * lo.y;
            acc[s].z += v * hi.x; acc[s].w += v * hi.y;
        }
    }
    float4* o = reinterpret_cast<float4*>(out + (size_t)row * DIN);
#pragma unroll
    for (int s = 0; s < 4; s++) o[tid + s * 256] = acc[s];
}

// ---------------- launch ----------------
extern "C" void kernel_launch(void* const* d_in, const int* in_sizes, int n_in,
                              void* d_out, int out_size) {
    const float* x     = (const float*)d_in[0];
    const float* W     = (const float*)d_in[1];
    const float* b_enc = (const float*)d_in[2];
    const float* b_dec = (const float*)d_in[3];
    float* out = (float*)d_out;

    convert_kernel<<<2368, 256>>>(x, W);

    dim3 g1(B_DIM / 128, DBN / 128);
    encode_gemm<<<g1, 256>>>(b_enc);

    topk_kernel<<<B_DIM, 256>>>();
    rescore_decode_kernel<<<B_DIM, 256>>>(x, W, b_enc, b_dec, out);
}

// round 15
// speedup vs baseline: 1.1086x; 1.1086x over previous
#include <cuda_runtime.h>
#include <cuda_bf16.h>
#include <cuda_fp16.h>
#include <cstdint>

#define B_DIM 4096
#define DIN   4096
#define DBN   32768
#define KSEL  64
#define CAND  80
#define BUF_CAP 1024
#define L2_CAP 512
#define FILTER_KEY 0xC000u   // monotonic key of +2.0 (bf16)

// ---------------- scratch (device globals: allocation-free) ----------------
__device__ __half        g_xh[(size_t)B_DIM * DIN];   // 32 MB  (GEMM A, fp16)
__device__ __half        g_wh[(size_t)DBN * DIN];     // 256 MB (GEMM B + decode, fp16)
__device__ __nv_bfloat16 g_a1[(size_t)B_DIM * DBN];   // 256 MB (bf16 scores)
__device__ int           g_cand[(size_t)B_DIM * CAND];

// ---------------- K0: fp32 -> fp16 convert (x and W; W shared by GEMM+decode) ----------------
__global__ void convert_kernel(const float* __restrict__ x, const float* __restrict__ w) {
    size_t nx = (size_t)B_DIM * DIN / 4;
    size_t nw = (size_t)DBN * DIN / 4;
    size_t stride = (size_t)gridDim.x * blockDim.x;
    for (size_t t = (size_t)blockIdx.x * blockDim.x + threadIdx.x; t < nx + nw; t += stride) {
        if (t < nx) {
            float4 v = ((const float4*)x)[t];
            __half2* o = reinterpret_cast<__half2*>(g_xh);
            o[2 * t]     = __floats2half2_rn(v.x, v.y);
            o[2 * t + 1] = __floats2half2_rn(v.z, v.w);
        } else {
            size_t u = t - nx;
            float4 v = ((const float4*)w)[u];
            __half2* o = reinterpret_cast<__half2*>(g_wh);
            o[2 * u]     = __floats2half2_rn(v.x, v.y);
            o[2 * u + 1] = __floats2half2_rn(v.z, v.w);
        }
    }
}

// ---------------- K1: fp16-input encode GEMM (a1 = bf16(x @ W^T + b_enc)) ----------------
// R5/R10 skeleton; fp16 inputs, fp32 accumulators (R13-validated speed = bf16).

__device__ __forceinline__ unsigned sw_off(int row, int c) {
    return (unsigned)(row * 64 + ((c ^ ((row >> 1) & 3)) << 4));
}

__global__ void __launch_bounds__(256) encode_gemm(const float* __restrict__ b_enc) {
    const int m0 = blockIdx.x * 128;
    const int n0 = blockIdx.y * 128;

    __shared__ __align__(16) __half sA[2][128 * 32];
    __shared__ __align__(16) __half sB[2][128 * 32];

    const int tid = threadIdx.x;
    const int wid = tid >> 5, lane = tid & 31;
    const int wm = wid >> 2, wn = wid & 3;

    unsigned sA_base = (unsigned)__cvta_generic_to_shared(&sA[0][0]);
    unsigned sB_base = (unsigned)__cvta_generic_to_shared(&sB[0][0]);

    const __half* gA = g_xh + (size_t)m0 * DIN;
    const __half* gB = g_wh + (size_t)n0 * DIN;

    float acc[4][4][4];
#pragma unroll
    for (int i = 0; i < 4; i++)
#pragma unroll
        for (int j = 0; j < 4; j++)
#pragma unroll
            for (int r = 0; r < 4; r++) acc[i][j][r] = 0.f;

#define LOAD_TILE(buf, kt)                                                              \
    do {                                                                                \
        _Pragma("unroll")                                                               \
        for (int _i = 0; _i < 2; _i++) {                                                \
            int cid = tid + 256 * _i;                                                   \
            int row = cid >> 2, c = cid & 3;                                            \
            unsigned off = sw_off(row, c);                                              \
            const __half* srcA = gA + (size_t)row * DIN + (kt) + c * 8;                 \
            const __half* srcB = gB + (size_t)row * DIN + (kt) + c * 8;                 \
            unsigned da = sA_base + (buf) * 8192u + off;                                \
            unsigned db = sB_base + (buf) * 8192u + off;                                \
            asm volatile("cp.async.cg.shared.global [%0],[%1],16;\n" ::"r"(da), "l"(srcA)); \
            asm volatile("cp.async.cg.shared.global [%0],[%1],16;\n" ::"r"(db), "l"(srcB)); \
        }                                                                               \
        asm volatile("cp.async.commit_group;\n");                                      \
    } while (0)

    LOAD_TILE(0, 0);
    const int NT = DIN / 32;
    for (int t = 0; t < NT; t++) {
        if (t + 1 < NT) {
            LOAD_TILE((t + 1) & 1, (t + 1) * 32);
            asm volatile("cp.async.wait_group 1;\n");
        } else {
            asm volatile("cp.async.wait_group 0;\n");
        }
        __syncthreads();
        const int buf = t & 1;
#pragma unroll
        for (int ks = 0; ks < 2; ks++) {
            unsigned a[4][4];
#pragma unroll
            for (int i = 0; i < 4; i++) {
                int row = wm * 64 + i * 16 + (lane & 7) + ((lane >> 3) & 1) * 8;
                int c   = ks * 2 + (lane >> 4);
                unsigned addr = sA_base + buf * 8192u + sw_off(row, c);
                asm volatile("ldmatrix.sync.aligned.m8n8.x4.shared.b16 {%0,%1,%2,%3},[%4];\n"
                             : "=r"(a[i][0]), "=r"(a[i][1]), "=r"(a[i][2]), "=r"(a[i][3])
                             : "r"(addr));
            }
            unsigned b[4][2];
#pragma unroll
            for (int jj = 0; jj < 2; jj++) {
                int row = wn * 32 + jj * 16 + ((lane >> 4) & 1) * 8 + (lane & 7);
                int c   = ks * 2 + ((lane >> 3) & 1);
                unsigned addr = sB_base + buf * 8192u + sw_off(row, c);
                unsigned r0, r1, r2, r3;
                asm volatile("ldmatrix.sync.aligned.m8n8.x4.shared.b16 {%0,%1,%2,%3},[%4];\n"
                             : "=r"(r0), "=r"(r1), "=r"(r2), "=r"(r3)
                             : "r"(addr));
                b[2 * jj][0] = r0; b[2 * jj][1] = r1;
                b[2 * jj + 1][0] = r2; b[2 * jj + 1][1] = r3;
            }
#pragma unroll
            for (int i = 0; i < 4; i++)
#pragma unroll
                for (int j = 0; j < 4; j++) {
                    asm volatile(
                        "mma.sync.aligned.m16n8k16.row.col.f32.f16.f16.f32 "
                        "{%0,%1,%2,%3},{%4,%5,%6,%7},{%8,%9},{%0,%1,%2,%3};\n"
                        : "+f"(acc[i][j][0]), "+f"(acc[i][j][1]),
                          "+f"(acc[i][j][2]), "+f"(acc[i][j][3])
                        : "r"(a[i][0]), "r"(a[i][1]), "r"(a[i][2]), "r"(a[i][3]),
                          "r"(b[j][0]), "r"(b[j][1]));
                }
        }
        __syncthreads();
    }
#undef LOAD_TILE

    // epilogue: + b_enc, store bf16 a1
    const int mrow = m0 + wm * 64;
    const int ncol = n0 + wn * 32;
#pragma unroll
    for (int i = 0; i < 4; i++) {
#pragma unroll
        for (int j = 0; j < 4; j++) {
            int r  = mrow + i * 16 + (lane >> 2);
            int cc = ncol + j * 8 + (lane & 3) * 2;
            float be0 = __ldg(&b_enc[cc]);
            float be1 = __ldg(&b_enc[cc + 1]);
            __nv_bfloat162 v0 = __floats2bfloat162_rn(acc[i][j][0] + be0, acc[i][j][1] + be1);
            __nv_bfloat162 v1 = __floats2bfloat162_rn(acc[i][j][2] + be0, acc[i][j][3] + be1);
            *reinterpret_cast<__nv_bfloat162*>(&g_a1[(size_t)r * DBN + cc])       = v0;
            *reinterpret_cast<__nv_bfloat162*>(&g_a1[(size_t)(r + 8) * DBN + cc]) = v1;
        }
    }
}

// ---------------- K2: filtered top-CAND with two-level threshold scan ----------------
__device__ __forceinline__ unsigned fkey16(unsigned u) {
    u &= 0xFFFFu;
    return (u & 0x8000u) ? ((~u) & 0xFFFFu) : (u | 0x8000u);  // order-preserving
}

__global__ void __launch_bounds__(256) topk_kernel() {
    const int row = blockIdx.x;
    const int tid = threadIdx.x;

    __shared__ unsigned buf[BUF_CAP];
    __shared__ unsigned list2[L2_CAP];
    __shared__ unsigned hist[4096];
    __shared__ unsigned part[256];
    __shared__ int bcnt, mcnt;
    __shared__ unsigned s_tbin;

    if (tid == 0) { bcnt = 0; mcnt = 0; }
    for (int i = tid; i < 4096; i += 256) hist[i] = 0;
    __syncthreads();

    const uint4* p4 = reinterpret_cast<const uint4*>(g_a1 + (size_t)row * DBN);
#pragma unroll 4
    for (int j = 0; j < 16; j++) {
        int vi = tid + 256 * j;
        uint4 v = p4[vi];
        unsigned w[4] = {v.x, v.y, v.z, v.w};
        int base = vi * 8;
#pragma unroll
        for (int q = 0; q < 4; q++) {
            unsigned k0 = fkey16(w[q]);
            unsigned k1 = fkey16(w[q] >> 16);
            if (k0 >= FILTER_KEY) {
                int pos = atomicAdd(&bcnt, 1);
                if (pos < BUF_CAP) buf[pos] = (k0 << 16) | (unsigned)(base + 2 * q);
            }
            if (k1 >= FILTER_KEY) {
                int pos = atomicAdd(&bcnt, 1);
                if (pos < BUF_CAP) buf[pos] = (k1 << 16) | (unsigned)(base + 2 * q + 1);
            }
        }
    }
    __syncthreads();

    bool fast_ok = (bcnt >= CAND && bcnt <= BUF_CAP);
    if (fast_ok) {
        const int n = bcnt;
        for (int e = tid; e < n; e += 256) {
            unsigned bin = (buf[e] >> 16) - FILTER_KEY;
            if (bin > 4095u) bin = 4095u;
            atomicAdd(&hist[bin], 1u);
        }
        __syncthreads();
        // two-level threshold scan: 256 partials of 16 bins, then <=256 + <=16 serial
        unsigned ps = 0;
#pragma unroll
        for (int b = 0; b < 16; b++) ps += hist[tid * 16 + b];
        part[tid] = ps;
        __syncthreads();
        if (tid == 0) {
            unsigned cum = 0;
            int g = 255;
            for (; g > 0; g--) {
                if (cum + part[g] >= CAND) break;
                cum += part[g];
            }
            int b = g * 16 + 15;
            for (; b > 0; b--) {
                unsigned c = hist[b];
                if (cum + c >= CAND) break;
                cum += c;
            }
            s_tbin = (unsigned)b;
        }
        __syncthreads();
        const unsigned tb = s_tbin;
        for (int e = tid; e < n; e += 256) {
            const unsigned pe = buf[e];
            unsigned bin = (pe >> 16) - FILTER_KEY;
            if (bin > 4095u) bin = 4095u;
            if (bin >= tb) {
                int pos = atomicAdd(&mcnt, 1);
                if (pos < L2_CAP) list2[pos] = pe;
            }
        }
        __syncthreads();
        if (mcnt <= L2_CAP) {
            const int m = mcnt;   // >= CAND by construction of tb
            for (int e = tid; e < m; e += 256) {
                const unsigned pe = list2[e];
                int rank = 0;
                for (int j2 = 0; j2 < m; j2++) rank += (list2[j2] > pe);
                if (rank < CAND) g_cand[(size_t)row * CAND + rank] = (int)(pe & 0xFFFFu);
            }
            return;
        }
    }

    // -------- fallback: full 4096-bin histogram (distribution-free) --------
    __syncthreads();
    for (int i = tid; i < 4096; i += 256) hist[i] = 0;
    if (tid == 0) { bcnt = 0; }
    __syncthreads();
#pragma unroll 4
    for (int j = 0; j < 16; j++) {
        uint4 v = p4[tid + 256 * j];
        unsigned w[4] = {v.x, v.y, v.z, v.w};
#pragma unroll
        for (int q = 0; q < 4; q++) {
            atomicAdd(&hist[fkey16(w[q]) >> 4], 1u);
            atomicAdd(&hist[fkey16(w[q] >> 16) >> 4], 1u);
        }
    }
    __syncthreads();
    {
        unsigned ps = 0;
#pragma unroll
        for (int b = 0; b < 16; b++) ps += hist[tid * 16 + b];
        part[tid] = ps;
    }
    __syncthreads();
    if (tid == 0) {
        unsigned cum = 0;
        int g = 255;
        for (; g > 0; g--) {
            if (cum + part[g] >= CAND) break;
            cum += part[g];
        }
        int b = g * 16 + 15;
        for (; b > 0; b--) {
            unsigned c = hist[b];
            if (cum + c >= CAND) break;
            cum += c;
        }
        s_tbin = (unsigned)b;
    }
    __syncthreads();
    const unsigned tb = s_tbin;
#pragma unroll 4
    for (int j = 0; j < 16; j++) {
        int vi = tid + 256 * j;
        uint4 v = p4[vi];
        unsigned w[4] = {v.x, v.y, v.z, v.w};
        int base = vi * 8;
#pragma unroll
        for (int q = 0; q < 4; q++) {
            unsigned k0 = fkey16(w[q]);
            unsigned k1 = fkey16(w[q] >> 16);
            if ((k0 >> 4) >= tb) {
                int pos = atomicAdd(&bcnt, 1);
                if (pos < BUF_CAP) buf[pos] = (k0 << 16) | (unsigned)(base + 2 * q);
            }
            if ((k1 >> 4) >= tb) {
                int pos = atomicAdd(&bcnt, 1);
                if (pos < BUF_CAP) buf[pos] = (k1 << 16) | (unsigned)(base + 2 * q + 1);
            }
        }
    }
    __syncthreads();
    const int n2 = bcnt < BUF_CAP ? bcnt : BUF_CAP;
    for (int e = tid; e < n2; e += 256) {
        const unsigned pe = buf[e];
        int rank = 0;
        for (int j2 = 0; j2 < n2; j2++) rank += (buf[j2] > pe);
        if (rank < CAND) g_cand[(size_t)row * CAND + rank] = (int)(pe & 0xFFFFu);
    }
}

// ---------------- K3: fused exact-rescore + top-64 + fp16-weight decode (R10) ----------------
__global__ void __launch_bounds__(256) rescore_decode_kernel(
    const float* __restrict__ x, const float* __restrict__ W,
    const float* __restrict__ b_enc, const float* __restrict__ b_dec,
    float* __restrict__ out) {
    const int row = blockIdx.x;
    const int tid = threadIdx.x;
    const int wid = tid >> 5, lane = tid & 31;

    __shared__ float  sx[DIN];
    __shared__ double sval[CAND];
    __shared__ int    scan_[CAND];
    __shared__ float  sv[KSEL];
    __shared__ int    si[KSEL];
    __shared__ int    cnt;

    const float4* xg  = reinterpret_cast<const float4*>(x + (size_t)row * DIN);
    float4*       sx4 = reinterpret_cast<float4*>(sx);
    for (int i = tid; i < DIN / 4; i += 256) sx4[i] = xg[i];
    if (tid == 0) cnt = 0;
    __syncthreads();

    for (int c = wid; c < CAND; c += 8) {
        const int idx = g_cand[(size_t)row * CAND + c];
        const float4* wv = reinterpret_cast<const float4*>(W + (size_t)idx * DIN);
        float s0 = 0.f, c0 = 0.f, s1 = 0.f, c1 = 0.f;
#define ACC(ss, cc, aa, bb)                              \
        {                                                \
            float p = (aa) * (bb);                       \
            float e = __fmaf_rn((aa), (bb), -p);         \
            float t = ss + p;                            \
            cc += (ss - t) + p;                          \
            ss = t;                                      \
            cc += e;                                     \
        }
        for (int i = lane; i < DIN / 4; i += 32) {
            float4 w = wv[i], xx = sx4[i];
            ACC(s0, c0, w.x, xx.x) ACC(s1, c1, w.y, xx.y)
            ACC(s0, c0, w.z, xx.z) ACC(s1, c1, w.w, xx.w)
        }
#undef ACC
        double d = ((double)s0 + (double)c0) + ((double)s1 + (double)c1);
#pragma unroll
        for (int o = 16; o; o >>= 1) d += __shfl_xor_sync(0xFFFFFFFFu, d, o);
        if (lane == 0) { sval[c] = d + (double)b_enc[idx]; scan_[c] = idx; }
    }
    __syncthreads();

    if (tid < CAND) {
        const double v = sval[tid];
        const int   ii = scan_[tid];
        int greater = 0;
        for (int j = 0; j < CAND; j++) {
            double u = sval[j];
            if (u > v || (u == v && scan_[j] < ii)) greater++;
        }
        if (greater < KSEL) {
            int slot = atomicAdd(&cnt, 1);
            sv[slot] = (float)v;
            si[slot] = ii;
        }
    }
    __syncthreads();

    const float4* bd = reinterpret_cast<const float4*>(b_dec);
    float4 acc[4];
#pragma unroll
    for (int s = 0; s < 4; s++) acc[s] = bd[tid + s * 256];

    for (int j = 0; j < KSEL; j++) {
        const float v = sv[j];
        const uint2* wr = reinterpret_cast<const uint2*>(g_wh + (size_t)si[j] * DIN);
#pragma unroll
        for (int s = 0; s < 4; s++) {
            uint2 hw = wr[tid + s * 256];
            float2 lo = __half22float2(*reinterpret_cast<__half2*>(&hw.x));
            float2 hi = __half22float2(*reinterpret_cast<__half2*>(&hw.y));
            acc[s].x += v * lo.x; acc[s].y += v * lo.y;
            acc[s].z += v * hi.x; acc[s].w += v * hi.y;
        }
    }
    float4* o = reinterpret_cast<float4*>(out + (size_t)row * DIN);
#pragma unroll
    for (int s = 0; s < 4; s++) o[tid + s * 256] = acc[s];
}

// ---------------- launch ----------------
extern "C" void kernel_launch(void* const* d_in, const int* in_sizes, int n_in,
                              void* d_out, int out_size) {
    const float* x     = (const float*)d_in[0];
    const float* W     = (const float*)d_in[1];
    const float* b_enc = (const float*)d_in[2];
    const float* b_dec = (const float*)d_in[3];
    float* out = (float*)d_out;

    convert_kernel<<<2368, 256>>>(x, W);

    dim3 g1(B_DIM / 128, DBN / 128);
    encode_gemm<<<g1, 256>>>(b_enc);

    topk_kernel<<<B_DIM, 256>>>();
    rescore_decode_kernel<<<B_DIM, 256>>>(x, W, b_enc, b_dec, out);
}